// round 10
// baseline (speedup 1.0000x reference)
#include <cuda_runtime.h>
#include <cuda_bf16.h>
#include <cstdint>
#include <cstddef>

// ---------------------------------------------------------------------------
// Problem constants
//   B=2, DIM=256, H=W=64, HEADS=8 (HC=32), HG=2 (GC=128), STRIDE=2,
//   WS=8 (NW=64 windows of WT=64 queries), RH=RW=32 (R=1024), MLP_HID=1024
// ---------------------------------------------------------------------------

#define NB      2
#define CDIM    256
#define HWPIX   4096            // 64*64
#define HEADS   8
#define HC      32
#define HG      2
#define GC      128
#define RPTS    1024            // R
#define NWIN    64              // NW
#define NPIX_S  65536           // NW * R
#define MLPH    1024

// ----------------------------- scratch ------------------------------------
__device__ float g_xaT [NB * HWPIX * CDIM];            // LN1 out, pixel-major
__device__ float g_q   [NB * CDIM * HWPIX];            // q conv out, C-major
__device__ float g_t1  [4 * 128 * 32 * 32];
__device__ float g_t2  [4 * 128 * 16 * 16];
__device__ float g_t3  [4 * 128 * 8 * 8];
__device__ float g_oT  [4 * 64 * 128];                 // bn+gelu out, pixel-major
__device__ float g_offr[4 * 2048 * 64];                // off4 out, C-major
__device__ __nv_bfloat16 g_pk [4 * HWPIX * CDIM];      // partial k maps, bf16 pixel-major
__device__ __nv_bfloat16 g_pv [4 * HWPIX * CDIM];      // partial v maps, bf16 pixel-major
__device__ __nv_bfloat16 g_kk [(size_t)NB * NPIX_S * CDIM];  // kk bf16 [(b,w,r),c]
__device__ __nv_bfloat16 g_vv [(size_t)NB * NPIX_S * CDIM];  // vv bf16
__device__ float g_attnT[NB * HWPIX * CDIM];           // attention out, pixel-major
__device__ float g_x2  [NB * HWPIX * CDIM];            // x + proj, pixel-major
__device__ float g_xmT [NB * HWPIX * CDIM];            // LN2 out, pixel-major
__device__ float g_hidT[(size_t)NB * HWPIX * MLPH];    // mlp hidden, pixel-major

// ----------------------------- helpers ------------------------------------
__device__ __forceinline__ float geluf(float v) {
    return 0.5f * v * (1.0f + erff(v * 0.70710678118654752f));
}

// tf32 round-to-nearest conversion (kept in f32 container).
__device__ __forceinline__ float to_tf32(float x) {
    uint32_t u;
    asm("cvt.rna.tf32.f32 %0, %1;" : "=r"(u) : "f"(x));
    return __uint_as_float(u);
}

// m16n8k8 TF32 tensor-core MMA (fp32 accumulate).
__device__ __forceinline__ void mma_tf32(float* d, const uint32_t* a, const uint32_t* b) {
    asm volatile(
        "mma.sync.aligned.m16n8k8.row.col.f32.tf32.tf32.f32 "
        "{%0,%1,%2,%3}, {%4,%5,%6,%7}, {%8,%9}, {%0,%1,%2,%3};"
        : "+f"(d[0]), "+f"(d[1]), "+f"(d[2]), "+f"(d[3])
        : "r"(a[0]), "r"(a[1]), "r"(a[2]), "r"(a[3]), "r"(b[0]), "r"(b[1]));
}

// Fast exp on the FMA pipe. Degree-5 poly for 2^f, rel err ~8e-5.
__device__ __forceinline__ float fexp(float x) {
    float y = x * 1.4426950408889634f;
    y = fmaxf(y, -126.0f);
    float fi = floorf(y);
    float f = y - fi;
    float p = 0.0013333558f;
    p = fmaf(p, f, 0.0096181291f);
    p = fmaf(p, f, 0.0555041087f);
    p = fmaf(p, f, 0.2402264923f);
    p = fmaf(p, f, 0.6931471806f);
    p = fmaf(p, f, 1.0f);
    int e = (int)fi;
    return p * __int_as_float((e + 127) << 23);
}

// unpack 8 bf16 (one uint4) to floats
__device__ __forceinline__ void unp8(const uint4& u, float* f) {
    const __nv_bfloat162* h = (const __nv_bfloat162*)&u;
    #pragma unroll
    for (int i = 0; i < 4; i++) {
        float2 t = __bfloat1622float2(h[i]);
        f[2 * i] = t.x; f[2 * i + 1] = t.y;
    }
}

// ----------------------------- LayerNorm -----------------------------------
__global__ __launch_bounds__(256) void ln_kernel(
    const float* __restrict__ in, const float* __restrict__ gam,
    const float* __restrict__ bet, float* __restrict__ outT,
    size_t bStride, size_t cStride, size_t pStride)
{
    int p  = blockIdx.x;            // 0..8191
    int b  = p >> 12;
    int hw = p & 4095;
    const float* ip = in + (size_t)b * bStride + (size_t)hw * pStride;
    int c = threadIdx.x;
    float v = ip[(size_t)c * cStride];
    float s1 = v, s2 = v * v;
    #pragma unroll
    for (int d = 16; d > 0; d >>= 1) {
        s1 += __shfl_xor_sync(0xffffffffu, s1, d);
        s2 += __shfl_xor_sync(0xffffffffu, s2, d);
    }
    __shared__ float sm1[8], sm2[8];
    __shared__ float mu_s, ri_s;
    int wid = c >> 5;
    if ((c & 31) == 0) { sm1[wid] = s1; sm2[wid] = s2; }
    __syncthreads();
    if (c == 0) {
        float t1 = 0.f, t2 = 0.f;
        #pragma unroll
        for (int i = 0; i < 8; i++) { t1 += sm1[i]; t2 += sm2[i]; }
        float mu  = t1 * (1.0f / 256.0f);
        float var = t2 * (1.0f / 256.0f) - mu * mu;
        mu_s = mu;
        ri_s = rsqrtf(var + 1e-5f);
    }
    __syncthreads();
    outT[(size_t)p * 256 + c] = (v - mu_s) * ri_s * gam[c] + bet[c];
}

// ----------------------------- GEMM (TN, TF32 tensor core) ------------------
// C[z] = A(MxK, lda) * B[z](NxK, ldb)^T (+bias)(gelu?)(+res?).
// BM=128, BN=64, BK=32; 8 warps (4 m x 2 n), each 32x32 via 2x4 m16n8k8 frags.
#define GF_OUT_NMAJOR 1
#define GF_RES_NMAJOR 2
#define GF_GELU       4
#define GF_GROUPED    8
#define GF_OUT_BF16   16

__global__ __launch_bounds__(256) void gemm_tn(
    const float* __restrict__ A, int lda,
    const float* __restrict__ Bm, int ldb, size_t bZ,
    const float* __restrict__ bias, const float* __restrict__ res,
    float* __restrict__ C, int M, int N, int K, int flags)
{
    __shared__ float As[128][36];
    __shared__ float Bs[64][36];
    const int b  = blockIdx.z;
    const int m0 = blockIdx.y * 128;
    const int n0 = blockIdx.x * 64;
    const float* Ab = A;
    const float* Bb;
    if (flags & GF_GROUPED) {
        Ab = A + (b & 1) * 128;
        Bb = Bm + (size_t)(b >> 1) * ((size_t)HWPIX * 256) + (b & 1) * 128;
    } else {
        Bb = Bm + (size_t)b * bZ;
    }
    const int tid  = threadIdx.x;
    const int warp = tid >> 5, lane = tid & 31;
    const int g = lane >> 2, tg = lane & 3;
    const int wm = warp & 3;
    const int wn = warp >> 2;

    float acc[2][4][4];
    #pragma unroll
    for (int mi = 0; mi < 2; mi++)
        #pragma unroll
        for (int nj = 0; nj < 4; nj++)
            #pragma unroll
            for (int e = 0; e < 4; e++) acc[mi][nj][e] = 0.f;

    for (int k0 = 0; k0 < K; k0 += 32) {
        #pragma unroll
        for (int i = 0; i < 4; i++) {
            int e = tid + i * 256;
            int row = e >> 3, c4 = (e & 7) << 2;
            float4 a = *(const float4*)(Ab + (size_t)(m0 + row) * lda + k0 + c4);
            As[row][c4    ] = to_tf32(a.x);
            As[row][c4 + 1] = to_tf32(a.y);
            As[row][c4 + 2] = to_tf32(a.z);
            As[row][c4 + 3] = to_tf32(a.w);
        }
        #pragma unroll
        for (int i = 0; i < 2; i++) {
            int e = tid + i * 256;
            int row = e >> 3, c4 = (e & 7) << 2;
            float4 v = *(const float4*)(Bb + (size_t)(n0 + row) * ldb + k0 + c4);
            Bs[row][c4    ] = to_tf32(v.x);
            Bs[row][c4 + 1] = to_tf32(v.y);
            Bs[row][c4 + 2] = to_tf32(v.z);
            Bs[row][c4 + 3] = to_tf32(v.w);
        }
        __syncthreads();

        #pragma unroll
        for (int kk = 0; kk < 4; kk++) {
            int kb = kk * 8;
            uint32_t af[2][4], bf[4][2];
            #pragma unroll
            for (int mi = 0; mi < 2; mi++) {
                int mr = wm * 32 + mi * 16;
                af[mi][0] = __float_as_uint(As[mr + g    ][kb + tg    ]);
                af[mi][1] = __float_as_uint(As[mr + g + 8][kb + tg    ]);
                af[mi][2] = __float_as_uint(As[mr + g    ][kb + tg + 4]);
                af[mi][3] = __float_as_uint(As[mr + g + 8][kb + tg + 4]);
            }
            #pragma unroll
            for (int nj = 0; nj < 4; nj++) {
                int nr = wn * 32 + nj * 8;
                bf[nj][0] = __float_as_uint(Bs[nr + g][kb + tg    ]);
                bf[nj][1] = __float_as_uint(Bs[nr + g][kb + tg + 4]);
            }
            #pragma unroll
            for (int mi = 0; mi < 2; mi++)
                #pragma unroll
                for (int nj = 0; nj < 4; nj++)
                    mma_tf32(acc[mi][nj], af[mi], bf[nj]);
        }
        __syncthreads();
    }

    #pragma unroll
    for (int mi = 0; mi < 2; mi++) {
        #pragma unroll
        for (int nj = 0; nj < 4; nj++) {
            int nc = n0 + wn * 32 + nj * 8 + tg * 2;
            #pragma unroll
            for (int e = 0; e < 4; e++) {
                int m = m0 + wm * 32 + mi * 16 + g + (e >> 1) * 8;
                int n = nc + (e & 1);
                float v = acc[mi][nj][e];
                if (bias) v += bias[m];
                if (flags & GF_GELU) v = geluf(v);
                if (res) {
                    size_t ri = (flags & GF_RES_NMAJOR)
                        ? ((size_t)b * N + n) * (size_t)M + m
                        : ((size_t)b * M + m) * (size_t)N + n;
                    v += res[ri];
                }
                size_t oi = (flags & GF_OUT_NMAJOR)
                    ? ((size_t)b * N + n) * (size_t)M + m
                    : ((size_t)b * M + m) * (size_t)N + n;
                if (flags & GF_OUT_BF16)
                    ((__nv_bfloat16*)C)[oi] = __float2bfloat16(v);
                else
                    C[oi] = v;
            }
        }
    }
}

// ------------------------ depthwise 3x3 stride-2 ---------------------------
__global__ void dw_conv(const float* __restrict__ in, const float* __restrict__ w,
                        float* __restrict__ out, int Hi, int Ho)
{
    int idx = blockIdx.x * blockDim.x + threadIdx.x;
    int total = 4 * 128 * Ho * Ho;
    if (idx >= total) return;
    int ox = idx % Ho;
    int oy = (idx / Ho) % Ho;
    int c  = (idx / (Ho * Ho)) % 128;
    int g  = idx / (Ho * Ho * 128);
    const float* ip = in + (size_t)(g * 128 + c) * Hi * Hi;
    const float* wp = w + c * 9;
    float s = 0.f;
    #pragma unroll
    for (int ky = 0; ky < 3; ky++) {
        int iy = oy * 2 - 1 + ky;
        if (iy < 0 || iy >= Hi) continue;
        #pragma unroll
        for (int kx = 0; kx < 3; kx++) {
            int ix = ox * 2 - 1 + kx;
            if (ix < 0 || ix >= Hi) continue;
            s = fmaf(ip[iy * Hi + ix], wp[ky * 3 + kx], s);
        }
    }
    out[idx] = s;
}

// ------------------------- BN + GELU + transpose ---------------------------
__global__ void bn_gelu_t(const float* __restrict__ t3, const float* __restrict__ g,
                          const float* __restrict__ b, const float* __restrict__ m,
                          const float* __restrict__ v, float* __restrict__ oT)
{
    int idx = blockIdx.x * blockDim.x + threadIdx.x;
    if (idx >= 4 * 128 * 64) return;
    int wsp = idx % 64;
    int c   = (idx / 64) % 128;
    int gg  = idx / (64 * 128);
    float x = t3[idx];
    x = (x - m[c]) * rsqrtf(v[c] + 1e-5f) * g[c] + b[c];
    x = geluf(x);
    oT[(size_t)(gg * 64 + wsp) * 128 + c] = x;
}

// ------------------------- fused k/v deformable sampling (bf16) ------------
__global__ __launch_bounds__(256) void sample_kv(
    const float* __restrict__ offr, const __nv_bfloat16* __restrict__ pkT,
    const __nv_bfloat16* __restrict__ pvT, const float* __restrict__ kb,
    const float* __restrict__ vb, __nv_bfloat16* __restrict__ kkT,
    __nv_bfloat16* __restrict__ vvT)
{
    int blk = blockIdx.x;           // b*65536 + w*1024 + r
    int b = blk >> 16;
    int w = (blk >> 10) & 63;
    int r = blk & 1023;
    int ri2 = (r >> 5) << 1;
    int ci2 = (r & 31) << 1;
    int o = threadIdx.x;

    float ak = kb[o], av = vb[o];
    #pragma unroll
    for (int hg = 0; hg < 2; hg++) {
        int g = b * 2 + hg;
        float offRow = offr[(size_t)(g * 2048 + r) * 64 + w];
        float offCol = offr[(size_t)(g * 2048 + 1024 + r) * 64 + w];
        float rows = fmaf(tanhf(offRow), 0.984375f, (float)ri2);
        float cols = fmaf(tanhf(offCol), 0.984375f, (float)ci2);
        float r0f = floorf(rows), c0f = floorf(cols);
        float fr = rows - r0f, fc = cols - c0f;
        int r0 = (int)r0f, c0 = (int)c0f;
        const __nv_bfloat16* pk = pkT + (size_t)g * HWPIX * 256 + o;
        const __nv_bfloat16* pv = pvT + (size_t)g * HWPIX * 256 + o;
        float w00 = (1.f - fr) * (1.f - fc), w01 = (1.f - fr) * fc;
        float w10 = fr * (1.f - fc),         w11 = fr * fc;
        if (r0 >= 0 && r0 < 64) {
            if (c0 >= 0 && c0 < 64) {
                size_t p = (size_t)(r0 * 64 + c0) * 256;
                ak = fmaf(__bfloat162float(pk[p]), w00, ak);
                av = fmaf(__bfloat162float(pv[p]), w00, av);
            }
            if (c0 + 1 >= 0 && c0 + 1 < 64) {
                size_t p = (size_t)(r0 * 64 + c0 + 1) * 256;
                ak = fmaf(__bfloat162float(pk[p]), w01, ak);
                av = fmaf(__bfloat162float(pv[p]), w01, av);
            }
        }
        if (r0 + 1 >= 0 && r0 + 1 < 64) {
            if (c0 >= 0 && c0 < 64) {
                size_t p = (size_t)((r0 + 1) * 64 + c0) * 256;
                ak = fmaf(__bfloat162float(pk[p]), w10, ak);
                av = fmaf(__bfloat162float(pv[p]), w10, av);
            }
            if (c0 + 1 >= 0 && c0 + 1 < 64) {
                size_t p = (size_t)((r0 + 1) * 64 + c0 + 1) * 256;
                ak = fmaf(__bfloat162float(pk[p]), w11, ak);
                av = fmaf(__bfloat162float(pv[p]), w11, av);
            }
        }
    }
    size_t oi = (size_t)blk * 256 + o;
    kkT[oi] = __float2bfloat16(ak);
    vvT[oi] = __float2bfloat16(av);
}

// ------------------------------ attention (TF32 tensor core, bf16 K/V) ------
__global__ __launch_bounds__(128) void attn_kernel(
    const float* __restrict__ qb, const __nv_bfloat16* __restrict__ kkT,
    const __nv_bfloat16* __restrict__ vvT, const float* __restrict__ pos,
    float* __restrict__ outT)
{
    __shared__ float Qs[64][36];    // q rows x 32c (tf32, pre-scaled)
    __shared__ float Ks[64][36];    // r rows x 32c (bf16-exact in f32)
    __shared__ float VsT[32][69];   // 32c x 64r
    __shared__ float Ps[64][68];    // q rows x 64r probs (tf32)

    const int w = blockIdx.x, h = blockIdx.y, b = blockIdx.z;
    const int wh = w >> 3, wwx = w & 7;
    const int tid = threadIdx.x;
    const int warp = tid >> 5, lane = tid & 31;
    const int g = lane >> 2, tg = lane & 3;

    // stage Q (scaled by C^-0.5 = 1/16, tf32)
    for (int e = tid; e < 2048; e += 128) {
        int qq = e >> 5, c = e & 31;
        int yy = (wh << 3) + (qq >> 3), xx = (wwx << 3) + (qq & 7);
        Qs[qq][c] = to_tf32(qb[(size_t)(b * 256 + h * 32 + c) * HWPIX + yy * 64 + xx] * 0.0625f);
    }

    const int qA = warp * 16 + g, qB = qA + 8;
    const int yA = (wh << 3) + (qA >> 3), xA = (wwx << 3) + (qA & 7);
    const int yB = (wh << 3) + (qB >> 3), xB = (wwx << 3) + (qB & 7);
    const float* poshA = pos + h * 127 * 127 + (63 - yA) * 127 + (63 - xA);
    const float* poshB = pos + h * 127 * 127 + (63 - yB) * 127 + (63 - xB);

    float mA = -1e30f, sA = 0.f, mB = -1e30f, sB = 0.f;
    float O[4][4];
    #pragma unroll
    for (int nj = 0; nj < 4; nj++)
        #pragma unroll
        for (int e = 0; e < 4; e++) O[nj][e] = 0.f;

    const size_t kvbase = ((size_t)b * NPIX_S + (size_t)w * 1024) * 256 + h * 32;
    const int srow = tid >> 1, shalf = tid & 1;   // staging: row 0..63, 16-ch half

    for (int r0 = 0; r0 < 1024; r0 += 64) {
        __syncthreads();
        // stage K [r][c] and V transposed [c][r] (bf16 -> f32, exact in tf32)
        {
            const __nv_bfloat16* kp = kkT + kvbase + (size_t)(r0 + srow) * 256 + shalf * 16;
            const __nv_bfloat16* vp = vvT + kvbase + (size_t)(r0 + srow) * 256 + shalf * 16;
            uint4 k0 = *(const uint4*)kp;
            uint4 k1 = *(const uint4*)(kp + 8);
            uint4 v0 = *(const uint4*)vp;
            uint4 v1 = *(const uint4*)(vp + 8);
            float kf[16], vf[16];
            unp8(k0, kf); unp8(k1, kf + 8);
            unp8(v0, vf); unp8(v1, vf + 8);
            #pragma unroll
            for (int j = 0; j < 16; j++) {
                Ks[srow][shalf * 16 + j] = kf[j];
                VsT[shalf * 16 + j][srow] = vf[j];
            }
        }
        __syncthreads();

        // S[16q x 64r] per warp = Q Kt
        float S[8][4];
        #pragma unroll
        for (int nj = 0; nj < 8; nj++)
            #pragma unroll
            for (int e = 0; e < 4; e++) S[nj][e] = 0.f;
        #pragma unroll
        for (int kk = 0; kk < 4; kk++) {
            int kb = kk * 8;
            uint32_t af[4];
            af[0] = __float_as_uint(Qs[warp * 16 + g    ][kb + tg    ]);
            af[1] = __float_as_uint(Qs[warp * 16 + g + 8][kb + tg    ]);
            af[2] = __float_as_uint(Qs[warp * 16 + g    ][kb + tg + 4]);
            af[3] = __float_as_uint(Qs[warp * 16 + g + 8][kb + tg + 4]);
            #pragma unroll
            for (int nj = 0; nj < 8; nj++) {
                uint32_t bf[2];
                bf[0] = __float_as_uint(Ks[nj * 8 + g][kb + tg    ]);
                bf[1] = __float_as_uint(Ks[nj * 8 + g][kb + tg + 4]);
                mma_tf32(S[nj], af, bf);
            }
        }

        // add relative-position bias
        #pragma unroll
        for (int nj = 0; nj < 8; nj++) {
            int r0c = r0 + nj * 8 + 2 * tg;
            int r1c = r0c + 1;
            int o0 = ((r0c >> 5) << 1) * 127 + ((r0c & 31) << 1);
            int o1 = ((r1c >> 5) << 1) * 127 + ((r1c & 31) << 1);
            S[nj][0] += poshA[o0];
            S[nj][1] += poshA[o1];
            S[nj][2] += poshB[o0];
            S[nj][3] += poshB[o1];
        }

        // online softmax (rows g, g+8; stats reduced over the 4 tg lanes)
        float mxA = -1e30f, mxB = -1e30f;
        #pragma unroll
        for (int nj = 0; nj < 8; nj++) {
            mxA = fmaxf(mxA, fmaxf(S[nj][0], S[nj][1]));
            mxB = fmaxf(mxB, fmaxf(S[nj][2], S[nj][3]));
        }
        mxA = fmaxf(mxA, __shfl_xor_sync(0xffffffffu, mxA, 1));
        mxA = fmaxf(mxA, __shfl_xor_sync(0xffffffffu, mxA, 2));
        mxB = fmaxf(mxB, __shfl_xor_sync(0xffffffffu, mxB, 1));
        mxB = fmaxf(mxB, __shfl_xor_sync(0xffffffffu, mxB, 2));
        float mnA = fmaxf(mA, mxA), mnB = fmaxf(mB, mxB);
        float corrA = fexp(mA - mnA), corrB = fexp(mB - mnB);
        mA = mnA; mB = mnB;

        float suA = 0.f, suB = 0.f;
        #pragma unroll
        for (int nj = 0; nj < 8; nj++) {
            float p0 = fexp(S[nj][0] - mnA);
            float p1 = fexp(S[nj][1] - mnA);
            float p2 = fexp(S[nj][2] - mnB);
            float p3 = fexp(S[nj][3] - mnB);
            suA += p0 + p1;
            suB += p2 + p3;
            int c0 = nj * 8 + 2 * tg;
            Ps[warp * 16 + g    ][c0    ] = to_tf32(p0);
            Ps[warp * 16 + g    ][c0 + 1] = to_tf32(p1);
            Ps[warp * 16 + g + 8][c0    ] = to_tf32(p2);
            Ps[warp * 16 + g + 8][c0 + 1] = to_tf32(p3);
        }
        suA += __shfl_xor_sync(0xffffffffu, suA, 1);
        suA += __shfl_xor_sync(0xffffffffu, suA, 2);
        suB += __shfl_xor_sync(0xffffffffu, suB, 1);
        suB += __shfl_xor_sync(0xffffffffu, suB, 2);
        sA = sA * corrA + suA;
        sB = sB * corrB + suB;

        // rescale O (c0,c1 = row g; c2,c3 = row g+8)
        #pragma unroll
        for (int nj = 0; nj < 4; nj++) {
            O[nj][0] *= corrA; O[nj][1] *= corrA;
            O[nj][2] *= corrB; O[nj][3] *= corrB;
        }
        __syncwarp();
        __syncthreads();

        // O += P Vt : A = Ps [16q x 64k], B = VsT [32n x 64k]
        #pragma unroll
        for (int kk = 0; kk < 8; kk++) {
            int kb = kk * 8;
            uint32_t af[4];
            af[0] = __float_as_uint(Ps[warp * 16 + g    ][kb + tg    ]);
            af[1] = __float_as_uint(Ps[warp * 16 + g + 8][kb + tg    ]);
            af[2] = __float_as_uint(Ps[warp * 16 + g    ][kb + tg + 4]);
            af[3] = __float_as_uint(Ps[warp * 16 + g + 8][kb + tg + 4]);
            #pragma unroll
            for (int nj = 0; nj < 4; nj++) {
                uint32_t bf[2];
                bf[0] = __float_as_uint(VsT[nj * 8 + g][kb + tg    ]);
                bf[1] = __float_as_uint(VsT[nj * 8 + g][kb + tg + 4]);
                mma_tf32(O[nj], af, bf);
            }
        }
    }

    // epilogue: normalize and write (pixel-major, head slice)
    float invA = 1.0f / sA, invB = 1.0f / sB;
    float* opA = outT + ((size_t)b * HWPIX + yA * 64 + xA) * 256 + h * 32;
    float* opB = outT + ((size_t)b * HWPIX + yB * 64 + xB) * 256 + h * 32;
    #pragma unroll
    for (int nj = 0; nj < 4; nj++) {
        int c = nj * 8 + 2 * tg;
        opA[c]     = O[nj][0] * invA;
        opA[c + 1] = O[nj][1] * invA;
        opB[c]     = O[nj][2] * invB;
        opB[c + 1] = O[nj][3] * invB;
    }
}

// ------------------------------ launch -------------------------------------
extern "C" void kernel_launch(void* const* d_in, const int* in_sizes, int n_in,
                              void* d_out, int out_size)
{
    const float* x      = (const float*)d_in[0];
    const float* ln1_g  = (const float*)d_in[1];
    const float* ln1_b  = (const float*)d_in[2];
    const float* q_w    = (const float*)d_in[3];
    const float* q_b    = (const float*)d_in[4];
    const float* k_w    = (const float*)d_in[5];
    const float* k_b    = (const float*)d_in[6];
    const float* v_w    = (const float*)d_in[7];
    const float* v_b    = (const float*)d_in[8];
    const float* off1_w = (const float*)d_in[9];
    const float* off2_w = (const float*)d_in[10];
    const float* off3_w = (const float*)d_in[11];
    const float* bn_g   = (const float*)d_in[12];
    const float* bn_b   = (const float*)d_in[13];
    const float* bn_m   = (const float*)d_in[14];
    const float* bn_v   = (const float*)d_in[15];
    const float* off4_w = (const float*)d_in[16];
    const float* pos    = (const float*)d_in[17];
    const float* proj_w = (const float*)d_in[18];
    const float* proj_b = (const float*)d_in[19];
    const float* ln2_g  = (const float*)d_in[20];
    const float* ln2_b  = (const float*)d_in[21];
    const float* mlp_w1 = (const float*)d_in[22];
    const float* mlp_b1 = (const float*)d_in[23];
    const float* mlp_w2 = (const float*)d_in[24];
    const float* mlp_b2 = (const float*)d_in[25];
    float* out = (float*)d_out;

    float *xaT, *q, *t1, *t2, *t3, *oT, *offr, *attnT, *x2, *xmT, *hidT;
    __nv_bfloat16 *pkB, *pvB, *kkB, *vvB;
    cudaGetSymbolAddress((void**)&xaT,   g_xaT);
    cudaGetSymbolAddress((void**)&q,     g_q);
    cudaGetSymbolAddress((void**)&t1,    g_t1);
    cudaGetSymbolAddress((void**)&t2,    g_t2);
    cudaGetSymbolAddress((void**)&t3,    g_t3);
    cudaGetSymbolAddress((void**)&oT,    g_oT);
    cudaGetSymbolAddress((void**)&offr,  g_offr);
    cudaGetSymbolAddress((void**)&pkB,   g_pk);
    cudaGetSymbolAddress((void**)&pvB,   g_pv);
    cudaGetSymbolAddress((void**)&kkB,   g_kk);
    cudaGetSymbolAddress((void**)&vvB,   g_vv);
    cudaGetSymbolAddress((void**)&attnT, g_attnT);
    cudaGetSymbolAddress((void**)&x2,    g_x2);
    cudaGetSymbolAddress((void**)&xmT,   g_xmT);
    cudaGetSymbolAddress((void**)&hidT,  g_hidT);

    // 1. LN1: x (B,C,HW) C-major -> xaT pixel-major
    ln_kernel<<<8192, 256>>>(x, ln1_g, ln1_b, xaT,
                             (size_t)CDIM * HWPIX, (size_t)HWPIX, (size_t)1);

    // 2. q = q_w @ xa + q_b  -> C-major (B,256,4096)
    gemm_tn<<<dim3(HWPIX / 64, CDIM / 128, NB), 256>>>(
        q_w, CDIM, xaT, CDIM, (size_t)HWPIX * CDIM,
        q_b, nullptr, q, CDIM, HWPIX, CDIM, 0);

    // 3. offset path: 3x depthwise stride-2 convs (q viewed as (4,128,64,64))
    dw_conv<<<(4 * 128 * 32 * 32 + 255) / 256, 256>>>(q,  off1_w, t1, 64, 32);
    dw_conv<<<(4 * 128 * 16 * 16 + 255) / 256, 256>>>(t1, off2_w, t2, 32, 16);
    dw_conv<<<(4 * 128 *  8 *  8 + 255) / 256, 256>>>(t2, off3_w, t3, 16, 8);

    // 4. BN + GELU, transpose to pixel-major
    bn_gelu_t<<<(4 * 128 * 64 + 255) / 256, 256>>>(t3, bn_g, bn_b, bn_m, bn_v, oT);

    // 5. off4: (2048x128) @ (64x128)^T per group -> offr C-major (4,2048,64)
    gemm_tn<<<dim3(1, 2048 / 128, 4), 256>>>(
        off4_w, 128, oT, 128, (size_t)64 * 128,
        nullptr, nullptr, offr, 2048, 64, 128, 0);

    // 6a/6b. partial conv maps -> bf16 pixel-major
    gemm_tn<<<dim3(HWPIX / 64, 2, 4), 256>>>(
        k_w, CDIM, xaT, CDIM, 0,
        nullptr, nullptr, (float*)pkB, CDIM, HWPIX, GC,
        GF_GROUPED | GF_OUT_NMAJOR | GF_OUT_BF16);
    gemm_tn<<<dim3(HWPIX / 64, 2, 4), 256>>>(
        v_w, CDIM, xaT, CDIM, 0,
        nullptr, nullptr, (float*)pvB, CDIM, HWPIX, GC,
        GF_GROUPED | GF_OUT_NMAJOR | GF_OUT_BF16);

    // 7. fused deformable sampling of partial maps -> kk/vv bf16 pixel-major
    sample_kv<<<NB * NPIX_S, 256>>>(offr, pkB, pvB, k_b, v_b, kkB, vvB);

    // 8. windowed attention with rel-pos bias -> attnT pixel-major
    attn_kernel<<<dim3(NWIN, HEADS, NB), 128>>>(q, kkB, vvB, pos, attnT);

    // 9. proj + residual(x, C-major) -> x2 pixel-major
    gemm_tn<<<dim3(HWPIX / 64, CDIM / 128, NB), 256>>>(
        proj_w, CDIM, attnT, CDIM, (size_t)HWPIX * CDIM,
        proj_b, x, x2, CDIM, HWPIX, CDIM, GF_OUT_NMAJOR);

    // 10. LN2 on x2 (pixel-major) -> xmT pixel-major
    ln_kernel<<<8192, 256>>>(x2, ln2_g, ln2_b, xmT,
                             (size_t)HWPIX * CDIM, (size_t)1, (size_t)CDIM);

    // 11. mlp1 + gelu -> hidT pixel-major (B,4096,1024)
    gemm_tn<<<dim3(HWPIX / 64, MLPH / 128, NB), 256>>>(
        mlp_w1, CDIM, xmT, CDIM, (size_t)HWPIX * CDIM,
        mlp_b1, nullptr, hidT, MLPH, HWPIX, CDIM, GF_OUT_NMAJOR | GF_GELU);

    // 12. mlp2 + residual(x2, pixel-major) -> out C-major (B,256,64,64)
    gemm_tn<<<dim3(HWPIX / 64, CDIM / 128, NB), 256>>>(
        mlp_w2, MLPH, hidT, MLPH, (size_t)HWPIX * MLPH,
        mlp_b2, x2, out, CDIM, HWPIX, MLPH, GF_RES_NMAJOR);
}

// round 11
// speedup vs baseline: 1.2267x; 1.2267x over previous
#include <cuda_runtime.h>
#include <cuda_bf16.h>
#include <cstdint>
#include <cstddef>

// ---------------------------------------------------------------------------
// Problem constants
//   B=2, DIM=256, H=W=64, HEADS=8 (HC=32), HG=2 (GC=128), STRIDE=2,
//   WS=8 (NW=64 windows of WT=64 queries), RH=RW=32 (R=1024), MLP_HID=1024
// ---------------------------------------------------------------------------

#define NB      2
#define CDIM    256
#define HWPIX   4096            // 64*64
#define HEADS   8
#define HC      32
#define HG      2
#define GC      128
#define RPTS    1024            // R
#define NWIN    64              // NW
#define NPIX_S  65536           // NW * R
#define MLPH    1024

// ----------------------------- scratch ------------------------------------
__device__ float g_xaT [NB * HWPIX * CDIM];            // LN1 out, pixel-major
__device__ float g_q   [NB * CDIM * HWPIX];            // q conv out, C-major
__device__ float g_t1  [4 * 128 * 32 * 32];
__device__ float g_t2  [4 * 128 * 16 * 16];
__device__ float g_t3  [4 * 128 * 8 * 8];
__device__ float g_oT  [4 * 64 * 128];                 // bn+gelu out, pixel-major
__device__ float g_offr[4 * 2048 * 64];                // off4 out, C-major
__device__ __nv_bfloat16 g_pk [4 * HWPIX * CDIM];      // partial k maps, bf16 pixel-major
__device__ __nv_bfloat16 g_pv [4 * HWPIX * CDIM];      // partial v maps, bf16 pixel-major
__device__ __nv_bfloat16 g_kk [(size_t)NB * NPIX_S * CDIM];  // kk bf16 [(b,w,r),c]
__device__ __nv_bfloat16 g_vv [(size_t)NB * NPIX_S * CDIM];  // vv bf16
__device__ float g_attnT[NB * HWPIX * CDIM];           // attention out, pixel-major
__device__ float g_x2  [NB * HWPIX * CDIM];            // x + proj, pixel-major
__device__ float g_xmT [NB * HWPIX * CDIM];            // LN2 out, pixel-major
__device__ float g_hidT[(size_t)NB * HWPIX * MLPH];    // mlp hidden, pixel-major

// ----------------------------- helpers ------------------------------------
__device__ __forceinline__ float geluf(float v) {
    return 0.5f * v * (1.0f + erff(v * 0.70710678118654752f));
}

// tf32 round-to-nearest conversion (kept in f32 container).
__device__ __forceinline__ float to_tf32(float x) {
    uint32_t u;
    asm("cvt.rna.tf32.f32 %0, %1;" : "=r"(u) : "f"(x));
    return __uint_as_float(u);
}

// m16n8k8 TF32 tensor-core MMA (fp32 accumulate).
__device__ __forceinline__ void mma_tf32(float* d, const uint32_t* a, const uint32_t* b) {
    asm volatile(
        "mma.sync.aligned.m16n8k8.row.col.f32.tf32.tf32.f32 "
        "{%0,%1,%2,%3}, {%4,%5,%6,%7}, {%8,%9}, {%0,%1,%2,%3};"
        : "+f"(d[0]), "+f"(d[1]), "+f"(d[2]), "+f"(d[3])
        : "r"(a[0]), "r"(a[1]), "r"(a[2]), "r"(a[3]), "r"(b[0]), "r"(b[1]));
}

// Fast exp on the FMA pipe. Degree-5 poly for 2^f, rel err ~8e-5.
__device__ __forceinline__ float fexp(float x) {
    float y = x * 1.4426950408889634f;
    y = fmaxf(y, -126.0f);
    float fi = floorf(y);
    float f = y - fi;
    float p = 0.0013333558f;
    p = fmaf(p, f, 0.0096181291f);
    p = fmaf(p, f, 0.0555041087f);
    p = fmaf(p, f, 0.2402264923f);
    p = fmaf(p, f, 0.6931471806f);
    p = fmaf(p, f, 1.0f);
    int e = (int)fi;
    return p * __int_as_float((e + 127) << 23);
}

// unpack 8 bf16 (one uint4) to floats
__device__ __forceinline__ void unp8(const uint4& u, float* f) {
    const __nv_bfloat162* h = (const __nv_bfloat162*)&u;
    #pragma unroll
    for (int i = 0; i < 4; i++) {
        float2 t = __bfloat1622float2(h[i]);
        f[2 * i] = t.x; f[2 * i + 1] = t.y;
    }
}

// ----------------------------- LayerNorm -----------------------------------
__global__ __launch_bounds__(256) void ln_kernel(
    const float* __restrict__ in, const float* __restrict__ gam,
    const float* __restrict__ bet, float* __restrict__ outT,
    size_t bStride, size_t cStride, size_t pStride)
{
    int p  = blockIdx.x;            // 0..8191
    int b  = p >> 12;
    int hw = p & 4095;
    const float* ip = in + (size_t)b * bStride + (size_t)hw * pStride;
    int c = threadIdx.x;
    float v = ip[(size_t)c * cStride];
    float s1 = v, s2 = v * v;
    #pragma unroll
    for (int d = 16; d > 0; d >>= 1) {
        s1 += __shfl_xor_sync(0xffffffffu, s1, d);
        s2 += __shfl_xor_sync(0xffffffffu, s2, d);
    }
    __shared__ float sm1[8], sm2[8];
    __shared__ float mu_s, ri_s;
    int wid = c >> 5;
    if ((c & 31) == 0) { sm1[wid] = s1; sm2[wid] = s2; }
    __syncthreads();
    if (c == 0) {
        float t1 = 0.f, t2 = 0.f;
        #pragma unroll
        for (int i = 0; i < 8; i++) { t1 += sm1[i]; t2 += sm2[i]; }
        float mu  = t1 * (1.0f / 256.0f);
        float var = t2 * (1.0f / 256.0f) - mu * mu;
        mu_s = mu;
        ri_s = rsqrtf(var + 1e-5f);
    }
    __syncthreads();
    outT[(size_t)p * 256 + c] = (v - mu_s) * ri_s * gam[c] + bet[c];
}

// ----------------------------- GEMM (TN, TF32 tensor core) ------------------
// C[z] = A(MxK, lda) * B[z](NxK, ldb)^T (+bias)(gelu?)(+res?).
// BM=128, BN=64, BK=32; 8 warps (4 m x 2 n), each 32x32 via 2x4 m16n8k8 frags.
#define GF_OUT_NMAJOR 1
#define GF_RES_NMAJOR 2
#define GF_GELU       4
#define GF_GROUPED    8
#define GF_OUT_BF16   16

__global__ __launch_bounds__(256) void gemm_tn(
    const float* __restrict__ A, int lda,
    const float* __restrict__ Bm, int ldb, size_t bZ,
    const float* __restrict__ bias, const float* __restrict__ res,
    float* __restrict__ C, int M, int N, int K, int flags)
{
    __shared__ float As[128][36];
    __shared__ float Bs[64][36];
    const int b  = blockIdx.z;
    const int m0 = blockIdx.y * 128;
    const int n0 = blockIdx.x * 64;
    const float* Ab = A;
    const float* Bb;
    if (flags & GF_GROUPED) {
        Ab = A + (b & 1) * 128;
        Bb = Bm + (size_t)(b >> 1) * ((size_t)HWPIX * 256) + (b & 1) * 128;
    } else {
        Bb = Bm + (size_t)b * bZ;
    }
    const int tid  = threadIdx.x;
    const int warp = tid >> 5, lane = tid & 31;
    const int g = lane >> 2, tg = lane & 3;
    const int wm = warp & 3;
    const int wn = warp >> 2;

    float acc[2][4][4];
    #pragma unroll
    for (int mi = 0; mi < 2; mi++)
        #pragma unroll
        for (int nj = 0; nj < 4; nj++)
            #pragma unroll
            for (int e = 0; e < 4; e++) acc[mi][nj][e] = 0.f;

    for (int k0 = 0; k0 < K; k0 += 32) {
        #pragma unroll
        for (int i = 0; i < 4; i++) {
            int e = tid + i * 256;
            int row = e >> 3, c4 = (e & 7) << 2;
            float4 a = *(const float4*)(Ab + (size_t)(m0 + row) * lda + k0 + c4);
            As[row][c4    ] = to_tf32(a.x);
            As[row][c4 + 1] = to_tf32(a.y);
            As[row][c4 + 2] = to_tf32(a.z);
            As[row][c4 + 3] = to_tf32(a.w);
        }
        #pragma unroll
        for (int i = 0; i < 2; i++) {
            int e = tid + i * 256;
            int row = e >> 3, c4 = (e & 7) << 2;
            float4 v = *(const float4*)(Bb + (size_t)(n0 + row) * ldb + k0 + c4);
            Bs[row][c4    ] = to_tf32(v.x);
            Bs[row][c4 + 1] = to_tf32(v.y);
            Bs[row][c4 + 2] = to_tf32(v.z);
            Bs[row][c4 + 3] = to_tf32(v.w);
        }
        __syncthreads();

        #pragma unroll
        for (int kk = 0; kk < 4; kk++) {
            int kb = kk * 8;
            uint32_t af[2][4], bf[4][2];
            #pragma unroll
            for (int mi = 0; mi < 2; mi++) {
                int mr = wm * 32 + mi * 16;
                af[mi][0] = __float_as_uint(As[mr + g    ][kb + tg    ]);
                af[mi][1] = __float_as_uint(As[mr + g + 8][kb + tg    ]);
                af[mi][2] = __float_as_uint(As[mr + g    ][kb + tg + 4]);
                af[mi][3] = __float_as_uint(As[mr + g + 8][kb + tg + 4]);
            }
            #pragma unroll
            for (int nj = 0; nj < 4; nj++) {
                int nr = wn * 32 + nj * 8;
                bf[nj][0] = __float_as_uint(Bs[nr + g][kb + tg    ]);
                bf[nj][1] = __float_as_uint(Bs[nr + g][kb + tg + 4]);
            }
            #pragma unroll
            for (int mi = 0; mi < 2; mi++)
                #pragma unroll
                for (int nj = 0; nj < 4; nj++)
                    mma_tf32(acc[mi][nj], af[mi], bf[nj]);
        }
        __syncthreads();
    }

    #pragma unroll
    for (int mi = 0; mi < 2; mi++) {
        #pragma unroll
        for (int nj = 0; nj < 4; nj++) {
            int nc = n0 + wn * 32 + nj * 8 + tg * 2;
            #pragma unroll
            for (int e = 0; e < 4; e++) {
                int m = m0 + wm * 32 + mi * 16 + g + (e >> 1) * 8;
                int n = nc + (e & 1);
                float v = acc[mi][nj][e];
                if (bias) v += bias[m];
                if (flags & GF_GELU) v = geluf(v);
                if (res) {
                    size_t ri = (flags & GF_RES_NMAJOR)
                        ? ((size_t)b * N + n) * (size_t)M + m
                        : ((size_t)b * M + m) * (size_t)N + n;
                    v += res[ri];
                }
                size_t oi = (flags & GF_OUT_NMAJOR)
                    ? ((size_t)b * N + n) * (size_t)M + m
                    : ((size_t)b * M + m) * (size_t)N + n;
                if (flags & GF_OUT_BF16)
                    ((__nv_bfloat16*)C)[oi] = __float2bfloat16(v);
                else
                    C[oi] = v;
            }
        }
    }
}

// ------------------------ depthwise 3x3 stride-2 ---------------------------
__global__ void dw_conv(const float* __restrict__ in, const float* __restrict__ w,
                        float* __restrict__ out, int Hi, int Ho)
{
    int idx = blockIdx.x * blockDim.x + threadIdx.x;
    int total = 4 * 128 * Ho * Ho;
    if (idx >= total) return;
    int ox = idx % Ho;
    int oy = (idx / Ho) % Ho;
    int c  = (idx / (Ho * Ho)) % 128;
    int g  = idx / (Ho * Ho * 128);
    const float* ip = in + (size_t)(g * 128 + c) * Hi * Hi;
    const float* wp = w + c * 9;
    float s = 0.f;
    #pragma unroll
    for (int ky = 0; ky < 3; ky++) {
        int iy = oy * 2 - 1 + ky;
        if (iy < 0 || iy >= Hi) continue;
        #pragma unroll
        for (int kx = 0; kx < 3; kx++) {
            int ix = ox * 2 - 1 + kx;
            if (ix < 0 || ix >= Hi) continue;
            s = fmaf(ip[iy * Hi + ix], wp[ky * 3 + kx], s);
        }
    }
    out[idx] = s;
}

// ------------------------- BN + GELU + transpose ---------------------------
__global__ void bn_gelu_t(const float* __restrict__ t3, const float* __restrict__ g,
                          const float* __restrict__ b, const float* __restrict__ m,
                          const float* __restrict__ v, float* __restrict__ oT)
{
    int idx = blockIdx.x * blockDim.x + threadIdx.x;
    if (idx >= 4 * 128 * 64) return;
    int wsp = idx % 64;
    int c   = (idx / 64) % 128;
    int gg  = idx / (64 * 128);
    float x = t3[idx];
    x = (x - m[c]) * rsqrtf(v[c] + 1e-5f) * g[c] + b[c];
    x = geluf(x);
    oT[(size_t)(gg * 64 + wsp) * 128 + c] = x;
}

// ------------------------- fused k/v deformable sampling (bf16) ------------
// Per-block geometry (offr loads, tanh, floor, validity, addresses) computed
// ONCE by threads 0/1 into smem — previously every one of the 256 threads
// redundantly ran the ~120-instr prologue (~130M redundant tanh chip-wide).
__global__ __launch_bounds__(256) void sample_kv(
    const float* __restrict__ offr, const __nv_bfloat16* __restrict__ pkT,
    const __nv_bfloat16* __restrict__ pvT, const float* __restrict__ kb,
    const float* __restrict__ vb, __nv_bfloat16* __restrict__ kkT,
    __nv_bfloat16* __restrict__ vvT)
{
    __shared__ float4 s_w[2];   // bilinear weights per group
    __shared__ int4   s_o[2];   // corner element offsets (pix*256), -1 = invalid
    int blk = blockIdx.x;       // b*65536 + w*1024 + r
    int b = blk >> 16;
    int w = (blk >> 10) & 63;
    int r = blk & 1023;
    int tid = threadIdx.x;

    if (tid < 2) {
        int g = b * 2 + tid;
        float offRow = offr[(size_t)(g * 2048 + r) * 64 + w];
        float offCol = offr[(size_t)(g * 2048 + 1024 + r) * 64 + w];
        float rows = fmaf(tanhf(offRow), 0.984375f, (float)((r >> 5) << 1));
        float cols = fmaf(tanhf(offCol), 0.984375f, (float)((r & 31) << 1));
        float r0f = floorf(rows), c0f = floorf(cols);
        float fr = rows - r0f, fc = cols - c0f;
        int r0 = (int)r0f, c0 = (int)c0f;
        bool rv0 = (r0 >= 0) && (r0 < 64);
        bool rv1 = (r0 + 1 >= 0) && (r0 + 1 < 64);
        bool cv0 = (c0 >= 0) && (c0 < 64);
        bool cv1 = (c0 + 1 >= 0) && (c0 + 1 < 64);
        int4 o;
        o.x = (rv0 && cv0) ? (r0 * 64 + c0) * 256 : -1;
        o.y = (rv0 && cv1) ? (r0 * 64 + c0 + 1) * 256 : -1;
        o.z = (rv1 && cv0) ? ((r0 + 1) * 64 + c0) * 256 : -1;
        o.w = (rv1 && cv1) ? ((r0 + 1) * 64 + c0 + 1) * 256 : -1;
        s_o[tid] = o;
        s_w[tid] = make_float4((1.f - fr) * (1.f - fc), (1.f - fr) * fc,
                               fr * (1.f - fc),         fr * fc);
    }
    __syncthreads();

    int o = tid;
    float ak = kb[o], av = vb[o];
    #pragma unroll
    for (int hg = 0; hg < 2; hg++) {
        const __nv_bfloat16* pk = pkT + (size_t)(b * 2 + hg) * HWPIX * 256 + o;
        const __nv_bfloat16* pv = pvT + (size_t)(b * 2 + hg) * HWPIX * 256 + o;
        int4   oo = s_o[hg];
        float4 ww = s_w[hg];
        if (oo.x >= 0) {
            ak = fmaf(__bfloat162float(pk[oo.x]), ww.x, ak);
            av = fmaf(__bfloat162float(pv[oo.x]), ww.x, av);
        }
        if (oo.y >= 0) {
            ak = fmaf(__bfloat162float(pk[oo.y]), ww.y, ak);
            av = fmaf(__bfloat162float(pv[oo.y]), ww.y, av);
        }
        if (oo.z >= 0) {
            ak = fmaf(__bfloat162float(pk[oo.z]), ww.z, ak);
            av = fmaf(__bfloat162float(pv[oo.z]), ww.z, av);
        }
        if (oo.w >= 0) {
            ak = fmaf(__bfloat162float(pk[oo.w]), ww.w, ak);
            av = fmaf(__bfloat162float(pv[oo.w]), ww.w, av);
        }
    }
    size_t oi = (size_t)blk * 256 + o;
    kkT[oi] = __float2bfloat16(ak);
    vvT[oi] = __float2bfloat16(av);
}

// ------------------------------ attention (TF32 tensor core, bf16 K/V) ------
__global__ __launch_bounds__(128) void attn_kernel(
    const float* __restrict__ qb, const __nv_bfloat16* __restrict__ kkT,
    const __nv_bfloat16* __restrict__ vvT, const float* __restrict__ pos,
    float* __restrict__ outT)
{
    __shared__ float Qs[64][36];    // q rows x 32c (tf32, pre-scaled)
    __shared__ float Ks[64][36];    // r rows x 32c (bf16-exact in f32)
    __shared__ float VsT[32][69];   // 32c x 64r
    __shared__ float Ps[64][68];    // q rows x 64r probs (tf32)

    const int w = blockIdx.x, h = blockIdx.y, b = blockIdx.z;
    const int wh = w >> 3, wwx = w & 7;
    const int tid = threadIdx.x;
    const int warp = tid >> 5, lane = tid & 31;
    const int g = lane >> 2, tg = lane & 3;

    // stage Q (scaled by C^-0.5 = 1/16, tf32)
    for (int e = tid; e < 2048; e += 128) {
        int qq = e >> 5, c = e & 31;
        int yy = (wh << 3) + (qq >> 3), xx = (wwx << 3) + (qq & 7);
        Qs[qq][c] = to_tf32(qb[(size_t)(b * 256 + h * 32 + c) * HWPIX + yy * 64 + xx] * 0.0625f);
    }

    const int qA = warp * 16 + g, qB = qA + 8;
    const int yA = (wh << 3) + (qA >> 3), xA = (wwx << 3) + (qA & 7);
    const int yB = (wh << 3) + (qB >> 3), xB = (wwx << 3) + (qB & 7);
    const float* poshA = pos + h * 127 * 127 + (63 - yA) * 127 + (63 - xA);
    const float* poshB = pos + h * 127 * 127 + (63 - yB) * 127 + (63 - xB);

    float mA = -1e30f, sA = 0.f, mB = -1e30f, sB = 0.f;
    float O[4][4];
    #pragma unroll
    for (int nj = 0; nj < 4; nj++)
        #pragma unroll
        for (int e = 0; e < 4; e++) O[nj][e] = 0.f;

    const size_t kvbase = ((size_t)b * NPIX_S + (size_t)w * 1024) * 256 + h * 32;
    const int srow = tid >> 1, shalf = tid & 1;   // staging: row 0..63, 16-ch half

    for (int r0 = 0; r0 < 1024; r0 += 64) {
        __syncthreads();
        // stage K [r][c] and V transposed [c][r] (bf16 -> f32, exact in tf32)
        {
            const __nv_bfloat16* kp = kkT + kvbase + (size_t)(r0 + srow) * 256 + shalf * 16;
            const __nv_bfloat16* vp = vvT + kvbase + (size_t)(r0 + srow) * 256 + shalf * 16;
            uint4 k0 = *(const uint4*)kp;
            uint4 k1 = *(const uint4*)(kp + 8);
            uint4 v0 = *(const uint4*)vp;
            uint4 v1 = *(const uint4*)(vp + 8);
            float kf[16], vf[16];
            unp8(k0, kf); unp8(k1, kf + 8);
            unp8(v0, vf); unp8(v1, vf + 8);
            #pragma unroll
            for (int j = 0; j < 16; j++) {
                Ks[srow][shalf * 16 + j] = kf[j];
                VsT[shalf * 16 + j][srow] = vf[j];
            }
        }
        __syncthreads();

        // S[16q x 64r] per warp = Q Kt
        float S[8][4];
        #pragma unroll
        for (int nj = 0; nj < 8; nj++)
            #pragma unroll
            for (int e = 0; e < 4; e++) S[nj][e] = 0.f;
        #pragma unroll
        for (int kk = 0; kk < 4; kk++) {
            int kb = kk * 8;
            uint32_t af[4];
            af[0] = __float_as_uint(Qs[warp * 16 + g    ][kb + tg    ]);
            af[1] = __float_as_uint(Qs[warp * 16 + g + 8][kb + tg    ]);
            af[2] = __float_as_uint(Qs[warp * 16 + g    ][kb + tg + 4]);
            af[3] = __float_as_uint(Qs[warp * 16 + g + 8][kb + tg + 4]);
            #pragma unroll
            for (int nj = 0; nj < 8; nj++) {
                uint32_t bf[2];
                bf[0] = __float_as_uint(Ks[nj * 8 + g][kb + tg    ]);
                bf[1] = __float_as_uint(Ks[nj * 8 + g][kb + tg + 4]);
                mma_tf32(S[nj], af, bf);
            }
        }

        // add relative-position bias
        #pragma unroll
        for (int nj = 0; nj < 8; nj++) {
            int r0c = r0 + nj * 8 + 2 * tg;
            int r1c = r0c + 1;
            int o0 = ((r0c >> 5) << 1) * 127 + ((r0c & 31) << 1);
            int o1 = ((r1c >> 5) << 1) * 127 + ((r1c & 31) << 1);
            S[nj][0] += poshA[o0];
            S[nj][1] += poshA[o1];
            S[nj][2] += poshB[o0];
            S[nj][3] += poshB[o1];
        }

        // online softmax (rows g, g+8; stats reduced over the 4 tg lanes)
        float mxA = -1e30f, mxB = -1e30f;
        #pragma unroll
        for (int nj = 0; nj < 8; nj++) {
            mxA = fmaxf(mxA, fmaxf(S[nj][0], S[nj][1]));
            mxB = fmaxf(mxB, fmaxf(S[nj][2], S[nj][3]));
        }
        mxA = fmaxf(mxA, __shfl_xor_sync(0xffffffffu, mxA, 1));
        mxA = fmaxf(mxA, __shfl_xor_sync(0xffffffffu, mxA, 2));
        mxB = fmaxf(mxB, __shfl_xor_sync(0xffffffffu, mxB, 1));
        mxB = fmaxf(mxB, __shfl_xor_sync(0xffffffffu, mxB, 2));
        float mnA = fmaxf(mA, mxA), mnB = fmaxf(mB, mxB);
        float corrA = fexp(mA - mnA), corrB = fexp(mB - mnB);
        mA = mnA; mB = mnB;

        float suA = 0.f, suB = 0.f;
        #pragma unroll
        for (int nj = 0; nj < 8; nj++) {
            float p0 = fexp(S[nj][0] - mnA);
            float p1 = fexp(S[nj][1] - mnA);
            float p2 = fexp(S[nj][2] - mnB);
            float p3 = fexp(S[nj][3] - mnB);
            suA += p0 + p1;
            suB += p2 + p3;
            int c0 = nj * 8 + 2 * tg;
            Ps[warp * 16 + g    ][c0    ] = to_tf32(p0);
            Ps[warp * 16 + g    ][c0 + 1] = to_tf32(p1);
            Ps[warp * 16 + g + 8][c0    ] = to_tf32(p2);
            Ps[warp * 16 + g + 8][c0 + 1] = to_tf32(p3);
        }
        suA += __shfl_xor_sync(0xffffffffu, suA, 1);
        suA += __shfl_xor_sync(0xffffffffu, suA, 2);
        suB += __shfl_xor_sync(0xffffffffu, suB, 1);
        suB += __shfl_xor_sync(0xffffffffu, suB, 2);
        sA = sA * corrA + suA;
        sB = sB * corrB + suB;

        // rescale O (c0,c1 = row g; c2,c3 = row g+8)
        #pragma unroll
        for (int nj = 0; nj < 4; nj++) {
            O[nj][0] *= corrA; O[nj][1] *= corrA;
            O[nj][2] *= corrB; O[nj][3] *= corrB;
        }
        __syncwarp();
        __syncthreads();

        // O += P Vt : A = Ps [16q x 64k], B = VsT [32n x 64k]
        #pragma unroll
        for (int kk = 0; kk < 8; kk++) {
            int kb = kk * 8;
            uint32_t af[4];
            af[0] = __float_as_uint(Ps[warp * 16 + g    ][kb + tg    ]);
            af[1] = __float_as_uint(Ps[warp * 16 + g + 8][kb + tg    ]);
            af[2] = __float_as_uint(Ps[warp * 16 + g    ][kb + tg + 4]);
            af[3] = __float_as_uint(Ps[warp * 16 + g + 8][kb + tg + 4]);
            #pragma unroll
            for (int nj = 0; nj < 4; nj++) {
                uint32_t bf[2];
                bf[0] = __float_as_uint(VsT[nj * 8 + g][kb + tg    ]);
                bf[1] = __float_as_uint(VsT[nj * 8 + g][kb + tg + 4]);
                mma_tf32(O[nj], af, bf);
            }
        }
    }

    // epilogue: normalize and write (pixel-major, head slice)
    float invA = 1.0f / sA, invB = 1.0f / sB;
    float* opA = outT + ((size_t)b * HWPIX + yA * 64 + xA) * 256 + h * 32;
    float* opB = outT + ((size_t)b * HWPIX + yB * 64 + xB) * 256 + h * 32;
    #pragma unroll
    for (int nj = 0; nj < 4; nj++) {
        int c = nj * 8 + 2 * tg;
        opA[c]     = O[nj][0] * invA;
        opA[c + 1] = O[nj][1] * invA;
        opB[c]     = O[nj][2] * invB;
        opB[c + 1] = O[nj][3] * invB;
    }
}

// ------------------------------ launch -------------------------------------
extern "C" void kernel_launch(void* const* d_in, const int* in_sizes, int n_in,
                              void* d_out, int out_size)
{
    const float* x      = (const float*)d_in[0];
    const float* ln1_g  = (const float*)d_in[1];
    const float* ln1_b  = (const float*)d_in[2];
    const float* q_w    = (const float*)d_in[3];
    const float* q_b    = (const float*)d_in[4];
    const float* k_w    = (const float*)d_in[5];
    const float* k_b    = (const float*)d_in[6];
    const float* v_w    = (const float*)d_in[7];
    const float* v_b    = (const float*)d_in[8];
    const float* off1_w = (const float*)d_in[9];
    const float* off2_w = (const float*)d_in[10];
    const float* off3_w = (const float*)d_in[11];
    const float* bn_g   = (const float*)d_in[12];
    const float* bn_b   = (const float*)d_in[13];
    const float* bn_m   = (const float*)d_in[14];
    const float* bn_v   = (const float*)d_in[15];
    const float* off4_w = (const float*)d_in[16];
    const float* pos    = (const float*)d_in[17];
    const float* proj_w = (const float*)d_in[18];
    const float* proj_b = (const float*)d_in[19];
    const float* ln2_g  = (const float*)d_in[20];
    const float* ln2_b  = (const float*)d_in[21];
    const float* mlp_w1 = (const float*)d_in[22];
    const float* mlp_b1 = (const float*)d_in[23];
    const float* mlp_w2 = (const float*)d_in[24];
    const float* mlp_b2 = (const float*)d_in[25];
    float* out = (float*)d_out;

    float *xaT, *q, *t1, *t2, *t3, *oT, *offr, *attnT, *x2, *xmT, *hidT;
    __nv_bfloat16 *pkB, *pvB, *kkB, *vvB;
    cudaGetSymbolAddress((void**)&xaT,   g_xaT);
    cudaGetSymbolAddress((void**)&q,     g_q);
    cudaGetSymbolAddress((void**)&t1,    g_t1);
    cudaGetSymbolAddress((void**)&t2,    g_t2);
    cudaGetSymbolAddress((void**)&t3,    g_t3);
    cudaGetSymbolAddress((void**)&oT,    g_oT);
    cudaGetSymbolAddress((void**)&offr,  g_offr);
    cudaGetSymbolAddress((void**)&pkB,   g_pk);
    cudaGetSymbolAddress((void**)&pvB,   g_pv);
    cudaGetSymbolAddress((void**)&kkB,   g_kk);
    cudaGetSymbolAddress((void**)&vvB,   g_vv);
    cudaGetSymbolAddress((void**)&attnT, g_attnT);
    cudaGetSymbolAddress((void**)&x2,    g_x2);
    cudaGetSymbolAddress((void**)&xmT,   g_xmT);
    cudaGetSymbolAddress((void**)&hidT,  g_hidT);

    // 1. LN1: x (B,C,HW) C-major -> xaT pixel-major
    ln_kernel<<<8192, 256>>>(x, ln1_g, ln1_b, xaT,
                             (size_t)CDIM * HWPIX, (size_t)HWPIX, (size_t)1);

    // 2. q = q_w @ xa + q_b  -> C-major (B,256,4096)
    gemm_tn<<<dim3(HWPIX / 64, CDIM / 128, NB), 256>>>(
        q_w, CDIM, xaT, CDIM, (size_t)HWPIX * CDIM,
        q_b, nullptr, q, CDIM, HWPIX, CDIM, 0);

    // 3. offset path: 3x depthwise stride-2 convs (q viewed as (4,128,64,64))
    dw_conv<<<(4 * 128 * 32 * 32 + 255) / 256, 256>>>(q,  off1_w, t1, 64, 32);
    dw_conv<<<(4 * 128 * 16 * 16 + 255) / 256, 256>>>(t1, off2_w, t2, 32, 16);
    dw_conv<<<(4 * 128 *  8 *  8 + 255) / 256, 256>>>(t2, off3_w, t3, 16, 8);

    // 4. BN + GELU, transpose to pixel-major
    bn_gelu_t<<<(4 * 128 * 64 + 255) / 256, 256>>>(t3, bn_g, bn_b, bn_m, bn_v, oT);

    // 5. off4: (2048x128) @ (64x128)^T per group -> offr C-major (4,2048,64)
    gemm_tn<<<dim3(1, 2048 / 128, 4), 256>>>(
        off4_w, 128, oT, 128, (size_t)64 * 128,
        nullptr, nullptr, offr, 2048, 64, 128, 0);

    // 6a/6b. partial conv maps -> bf16 pixel-major
    gemm_tn<<<dim3(HWPIX / 64, 2, 4), 256>>>(
        k_w, CDIM, xaT, CDIM, 0,
        nullptr, nullptr, (float*)pkB, CDIM, HWPIX, GC,
        GF_GROUPED | GF_OUT_NMAJOR | GF_OUT_BF16);
    gemm_tn<<<dim3(HWPIX / 64, 2, 4), 256>>>(
        v_w, CDIM, xaT, CDIM, 0,
        nullptr, nullptr, (float*)pvB, CDIM, HWPIX, GC,
        GF_GROUPED | GF_OUT_NMAJOR | GF_OUT_BF16);

    // 7. fused deformable sampling of partial maps -> kk/vv bf16 pixel-major
    sample_kv<<<NB * NPIX_S, 256>>>(offr, pkB, pvB, k_b, v_b, kkB, vvB);

    // 8. windowed attention with rel-pos bias -> attnT pixel-major
    attn_kernel<<<dim3(NWIN, HEADS, NB), 128>>>(q, kkB, vvB, pos, attnT);

    // 9. proj + residual(x, C-major) -> x2 pixel-major
    gemm_tn<<<dim3(HWPIX / 64, CDIM / 128, NB), 256>>>(
        proj_w, CDIM, attnT, CDIM, (size_t)HWPIX * CDIM,
        proj_b, x, x2, CDIM, HWPIX, CDIM, GF_OUT_NMAJOR);

    // 10. LN2 on x2 (pixel-major) -> xmT pixel-major
    ln_kernel<<<8192, 256>>>(x2, ln2_g, ln2_b, xmT,
                             (size_t)HWPIX * CDIM, (size_t)1, (size_t)CDIM);

    // 11. mlp1 + gelu -> hidT pixel-major (B,4096,1024)
    gemm_tn<<<dim3(HWPIX / 64, MLPH / 128, NB), 256>>>(
        mlp_w1, CDIM, xmT, CDIM, (size_t)HWPIX * CDIM,
        mlp_b1, nullptr, hidT, MLPH, HWPIX, CDIM, GF_OUT_NMAJOR | GF_GELU);

    // 12. mlp2 + residual(x2, pixel-major) -> out C-major (B,256,64,64)
    gemm_tn<<<dim3(HWPIX / 64, CDIM / 128, NB), 256>>>(
        mlp_w2, MLPH, hidT, MLPH, (size_t)HWPIX * MLPH,
        mlp_b2, x2, out, CDIM, HWPIX, MLPH, GF_RES_NMAJOR);
}

// round 12
// speedup vs baseline: 1.3769x; 1.1224x over previous
#include <cuda_runtime.h>
#include <cuda_bf16.h>
#include <cstdint>
#include <cstddef>

// ---------------------------------------------------------------------------
// Problem constants
//   B=2, DIM=256, H=W=64, HEADS=8 (HC=32), HG=2 (GC=128), STRIDE=2,
//   WS=8 (NW=64 windows of WT=64 queries), RH=RW=32 (R=1024), MLP_HID=1024
// ---------------------------------------------------------------------------

#define NB      2
#define CDIM    256
#define HWPIX   4096            // 64*64
#define HEADS   8
#define HC      32
#define HG      2
#define GC      128
#define RPTS    1024            // R
#define NWIN    64              // NW
#define NPIX_S  65536           // NW * R
#define MLPH    1024

// ----------------------------- scratch ------------------------------------
__device__ float g_xaT [NB * HWPIX * CDIM];            // LN1 out, pixel-major
__device__ float g_q   [NB * CDIM * HWPIX];            // q conv out, C-major
__device__ float g_t1  [4 * 128 * 32 * 32];
__device__ float g_t2  [4 * 128 * 16 * 16];
__device__ float g_t3  [4 * 128 * 8 * 8];
__device__ float g_oT  [4 * 64 * 128];                 // bn+gelu out, pixel-major
__device__ float g_offr[4 * 2048 * 64];                // off4 out, C-major
__device__ __nv_bfloat16 g_pk [4 * HWPIX * CDIM];      // partial k maps, bf16 pixel-major
__device__ __nv_bfloat16 g_pv [4 * HWPIX * CDIM];      // partial v maps, bf16 pixel-major
__device__ float g_attnT[NB * HWPIX * CDIM];           // attention out, pixel-major
__device__ float g_x2  [NB * HWPIX * CDIM];            // x + proj, pixel-major
__device__ float g_xmT [NB * HWPIX * CDIM];            // LN2 out, pixel-major
__device__ float g_hidT[(size_t)NB * HWPIX * MLPH];    // mlp hidden, pixel-major

// ----------------------------- helpers ------------------------------------
__device__ __forceinline__ float geluf(float v) {
    return 0.5f * v * (1.0f + erff(v * 0.70710678118654752f));
}

// tf32 round-to-nearest conversion (kept in f32 container).
__device__ __forceinline__ float to_tf32(float x) {
    uint32_t u;
    asm("cvt.rna.tf32.f32 %0, %1;" : "=r"(u) : "f"(x));
    return __uint_as_float(u);
}

// m16n8k8 TF32 tensor-core MMA (fp32 accumulate).
__device__ __forceinline__ void mma_tf32(float* d, const uint32_t* a, const uint32_t* b) {
    asm volatile(
        "mma.sync.aligned.m16n8k8.row.col.f32.tf32.tf32.f32 "
        "{%0,%1,%2,%3}, {%4,%5,%6,%7}, {%8,%9}, {%0,%1,%2,%3};"
        : "+f"(d[0]), "+f"(d[1]), "+f"(d[2]), "+f"(d[3])
        : "r"(a[0]), "r"(a[1]), "r"(a[2]), "r"(a[3]), "r"(b[0]), "r"(b[1]));
}

// Fast exp on the FMA pipe. Degree-5 poly for 2^f, rel err ~8e-5.
__device__ __forceinline__ float fexp(float x) {
    float y = x * 1.4426950408889634f;
    y = fmaxf(y, -126.0f);
    float fi = floorf(y);
    float f = y - fi;
    float p = 0.0013333558f;
    p = fmaf(p, f, 0.0096181291f);
    p = fmaf(p, f, 0.0555041087f);
    p = fmaf(p, f, 0.2402264923f);
    p = fmaf(p, f, 0.6931471806f);
    p = fmaf(p, f, 1.0f);
    int e = (int)fi;
    return p * __int_as_float((e + 127) << 23);
}

// unpack 8 bf16 (one uint4) to floats
__device__ __forceinline__ void unp8(const uint4& u, float* f) {
    const __nv_bfloat162* h = (const __nv_bfloat162*)&u;
    #pragma unroll
    for (int i = 0; i < 4; i++) {
        float2 t = __bfloat1622float2(h[i]);
        f[2 * i] = t.x; f[2 * i + 1] = t.y;
    }
}

// ----------------------------- LayerNorm -----------------------------------
__global__ __launch_bounds__(256) void ln_kernel(
    const float* __restrict__ in, const float* __restrict__ gam,
    const float* __restrict__ bet, float* __restrict__ outT,
    size_t bStride, size_t cStride, size_t pStride)
{
    int p  = blockIdx.x;            // 0..8191
    int b  = p >> 12;
    int hw = p & 4095;
    const float* ip = in + (size_t)b * bStride + (size_t)hw * pStride;
    int c = threadIdx.x;
    float v = ip[(size_t)c * cStride];
    float s1 = v, s2 = v * v;
    #pragma unroll
    for (int d = 16; d > 0; d >>= 1) {
        s1 += __shfl_xor_sync(0xffffffffu, s1, d);
        s2 += __shfl_xor_sync(0xffffffffu, s2, d);
    }
    __shared__ float sm1[8], sm2[8];
    __shared__ float mu_s, ri_s;
    int wid = c >> 5;
    if ((c & 31) == 0) { sm1[wid] = s1; sm2[wid] = s2; }
    __syncthreads();
    if (c == 0) {
        float t1 = 0.f, t2 = 0.f;
        #pragma unroll
        for (int i = 0; i < 8; i++) { t1 += sm1[i]; t2 += sm2[i]; }
        float mu  = t1 * (1.0f / 256.0f);
        float var = t2 * (1.0f / 256.0f) - mu * mu;
        mu_s = mu;
        ri_s = rsqrtf(var + 1e-5f);
    }
    __syncthreads();
    outT[(size_t)p * 256 + c] = (v - mu_s) * ri_s * gam[c] + bet[c];
}

// ----------------------------- GEMM (TN, TF32 tensor core) ------------------
// C[z] = A(MxK, lda) * B[z](NxK, ldb)^T (+bias)(gelu?)(+res?).
// BM=128, BN=64, BK=32; 8 warps (4 m x 2 n), each 32x32 via 2x4 m16n8k8 frags.
#define GF_OUT_NMAJOR 1
#define GF_RES_NMAJOR 2
#define GF_GELU       4
#define GF_GROUPED    8
#define GF_OUT_BF16   16

__global__ __launch_bounds__(256) void gemm_tn(
    const float* __restrict__ A, int lda,
    const float* __restrict__ Bm, int ldb, size_t bZ,
    const float* __restrict__ bias, const float* __restrict__ res,
    float* __restrict__ C, int M, int N, int K, int flags)
{
    __shared__ float As[128][36];
    __shared__ float Bs[64][36];
    const int b  = blockIdx.z;
    const int m0 = blockIdx.y * 128;
    const int n0 = blockIdx.x * 64;
    const float* Ab = A;
    const float* Bb;
    if (flags & GF_GROUPED) {
        Ab = A + (b & 1) * 128;
        Bb = Bm + (size_t)(b >> 1) * ((size_t)HWPIX * 256) + (b & 1) * 128;
    } else {
        Bb = Bm + (size_t)b * bZ;
    }
    const int tid  = threadIdx.x;
    const int warp = tid >> 5, lane = tid & 31;
    const int g = lane >> 2, tg = lane & 3;
    const int wm = warp & 3;
    const int wn = warp >> 2;

    float acc[2][4][4];
    #pragma unroll
    for (int mi = 0; mi < 2; mi++)
        #pragma unroll
        for (int nj = 0; nj < 4; nj++)
            #pragma unroll
            for (int e = 0; e < 4; e++) acc[mi][nj][e] = 0.f;

    for (int k0 = 0; k0 < K; k0 += 32) {
        #pragma unroll
        for (int i = 0; i < 4; i++) {
            int e = tid + i * 256;
            int row = e >> 3, c4 = (e & 7) << 2;
            float4 a = *(const float4*)(Ab + (size_t)(m0 + row) * lda + k0 + c4);
            As[row][c4    ] = to_tf32(a.x);
            As[row][c4 + 1] = to_tf32(a.y);
            As[row][c4 + 2] = to_tf32(a.z);
            As[row][c4 + 3] = to_tf32(a.w);
        }
        #pragma unroll
        for (int i = 0; i < 2; i++) {
            int e = tid + i * 256;
            int row = e >> 3, c4 = (e & 7) << 2;
            float4 v = *(const float4*)(Bb + (size_t)(n0 + row) * ldb + k0 + c4);
            Bs[row][c4    ] = to_tf32(v.x);
            Bs[row][c4 + 1] = to_tf32(v.y);
            Bs[row][c4 + 2] = to_tf32(v.z);
            Bs[row][c4 + 3] = to_tf32(v.w);
        }
        __syncthreads();

        #pragma unroll
        for (int kk = 0; kk < 4; kk++) {
            int kb = kk * 8;
            uint32_t af[2][4], bf[4][2];
            #pragma unroll
            for (int mi = 0; mi < 2; mi++) {
                int mr = wm * 32 + mi * 16;
                af[mi][0] = __float_as_uint(As[mr + g    ][kb + tg    ]);
                af[mi][1] = __float_as_uint(As[mr + g + 8][kb + tg    ]);
                af[mi][2] = __float_as_uint(As[mr + g    ][kb + tg + 4]);
                af[mi][3] = __float_as_uint(As[mr + g + 8][kb + tg + 4]);
            }
            #pragma unroll
            for (int nj = 0; nj < 4; nj++) {
                int nr = wn * 32 + nj * 8;
                bf[nj][0] = __float_as_uint(Bs[nr + g][kb + tg    ]);
                bf[nj][1] = __float_as_uint(Bs[nr + g][kb + tg + 4]);
            }
            #pragma unroll
            for (int mi = 0; mi < 2; mi++)
                #pragma unroll
                for (int nj = 0; nj < 4; nj++)
                    mma_tf32(acc[mi][nj], af[mi], bf[nj]);
        }
        __syncthreads();
    }

    #pragma unroll
    for (int mi = 0; mi < 2; mi++) {
        #pragma unroll
        for (int nj = 0; nj < 4; nj++) {
            int nc = n0 + wn * 32 + nj * 8 + tg * 2;
            #pragma unroll
            for (int e = 0; e < 4; e++) {
                int m = m0 + wm * 32 + mi * 16 + g + (e >> 1) * 8;
                int n = nc + (e & 1);
                float v = acc[mi][nj][e];
                if (bias) v += bias[m];
                if (flags & GF_GELU) v = geluf(v);
                if (res) {
                    size_t ri = (flags & GF_RES_NMAJOR)
                        ? ((size_t)b * N + n) * (size_t)M + m
                        : ((size_t)b * M + m) * (size_t)N + n;
                    v += res[ri];
                }
                size_t oi = (flags & GF_OUT_NMAJOR)
                    ? ((size_t)b * N + n) * (size_t)M + m
                    : ((size_t)b * M + m) * (size_t)N + n;
                if (flags & GF_OUT_BF16)
                    ((__nv_bfloat16*)C)[oi] = __float2bfloat16(v);
                else
                    C[oi] = v;
            }
        }
    }
}

// ------------------------ depthwise 3x3 stride-2 ---------------------------
__global__ void dw_conv(const float* __restrict__ in, const float* __restrict__ w,
                        float* __restrict__ out, int Hi, int Ho)
{
    int idx = blockIdx.x * blockDim.x + threadIdx.x;
    int total = 4 * 128 * Ho * Ho;
    if (idx >= total) return;
    int ox = idx % Ho;
    int oy = (idx / Ho) % Ho;
    int c  = (idx / (Ho * Ho)) % 128;
    int g  = idx / (Ho * Ho * 128);
    const float* ip = in + (size_t)(g * 128 + c) * Hi * Hi;
    const float* wp = w + c * 9;
    float s = 0.f;
    #pragma unroll
    for (int ky = 0; ky < 3; ky++) {
        int iy = oy * 2 - 1 + ky;
        if (iy < 0 || iy >= Hi) continue;
        #pragma unroll
        for (int kx = 0; kx < 3; kx++) {
            int ix = ox * 2 - 1 + kx;
            if (ix < 0 || ix >= Hi) continue;
            s = fmaf(ip[iy * Hi + ix], wp[ky * 3 + kx], s);
        }
    }
    out[idx] = s;
}

// ------------------------- BN + GELU + transpose ---------------------------
__global__ void bn_gelu_t(const float* __restrict__ t3, const float* __restrict__ g,
                          const float* __restrict__ b, const float* __restrict__ m,
                          const float* __restrict__ v, float* __restrict__ oT)
{
    int idx = blockIdx.x * blockDim.x + threadIdx.x;
    if (idx >= 4 * 128 * 64) return;
    int wsp = idx % 64;
    int c   = (idx / 64) % 128;
    int gg  = idx / (64 * 128);
    float x = t3[idx];
    x = (x - m[c]) * rsqrtf(v[c] + 1e-5f) * g[c] + b[c];
    x = geluf(x);
    oT[(size_t)(gg * 64 + wsp) * 128 + c] = x;
}

// ------------- attention with FUSED deformable k/v sampling -----------------
// One block per (b, head, window), 128 threads = 4 warps. Per 64-r tile:
//  (1) 128 threads compute 128 (r, group) sampling geometries (tanh/floor/
//      validity) into smem — one each;
//  (2) staging threads gather 8 predicated 32B bf16 corner rows per tensor
//      from L2-resident pk/pv, blend in fp32 (+bias), store tf32 to Ks/VsT;
//  (3) S = Q·K^T (m16n8k8), bias, online softmax, O += P·V — unchanged.
// This deletes the 131072-CTA sampler kernel and the 268MB kk/vv round-trip.
__global__ __launch_bounds__(128) void attn_kernel(
    const float* __restrict__ qb, const float* __restrict__ offr,
    const __nv_bfloat16* __restrict__ pkT, const __nv_bfloat16* __restrict__ pvT,
    const float* __restrict__ kb, const float* __restrict__ vb,
    const float* __restrict__ pos, float* __restrict__ outT)
{
    __shared__ float Qs[64][36];    // q rows x 32c (tf32, pre-scaled)
    __shared__ float Ks[64][36];    // r rows x 32c (tf32, sampled k)
    __shared__ float VsT[32][69];   // 32c x 64r  (tf32, sampled v)
    __shared__ float Ps[64][68];    // q rows x 64r probs (tf32)
    __shared__ int2   s_go[64][2];  // corner pixels: (r0*64+c0) packed, -1 invalid
    __shared__ float4 s_gw[64][2];  // bilinear weights
    __shared__ int    s_gp[64][2][4]; // 4 corner pixel indices (-1 invalid)
    __shared__ float  s_kb[32], s_vb[32];

    const int w = blockIdx.x, h = blockIdx.y, b = blockIdx.z;
    const int wh = w >> 3, wwx = w & 7;
    const int tid = threadIdx.x;
    const int warp = tid >> 5, lane = tid & 31;
    const int g = lane >> 2, tg = lane & 3;

    // bias slices for this head
    if (tid < 32)       s_kb[tid] = kb[h * 32 + tid];
    else if (tid < 64)  s_vb[tid - 32] = vb[h * 32 + tid - 32];

    // stage Q (scaled by C^-0.5 = 1/16, tf32)
    for (int e = tid; e < 2048; e += 128) {
        int qq = e >> 5, c = e & 31;
        int yy = (wh << 3) + (qq >> 3), xx = (wwx << 3) + (qq & 7);
        Qs[qq][c] = to_tf32(qb[(size_t)(b * 256 + h * 32 + c) * HWPIX + yy * 64 + xx] * 0.0625f);
    }

    const int qA = warp * 16 + g, qB = qA + 8;
    const int yA = (wh << 3) + (qA >> 3), xA = (wwx << 3) + (qA & 7);
    const int yB = (wh << 3) + (qB >> 3), xB = (wwx << 3) + (qB & 7);
    const float* poshA = pos + h * 127 * 127 + (63 - yA) * 127 + (63 - xA);
    const float* poshB = pos + h * 127 * 127 + (63 - yB) * 127 + (63 - xB);

    float mA = -1e30f, sA = 0.f, mB = -1e30f, sB = 0.f;
    float O[4][4];
    #pragma unroll
    for (int nj = 0; nj < 4; nj++)
        #pragma unroll
        for (int e = 0; e < 4; e++) O[nj][e] = 0.f;

    const int srow = tid >> 1, shalf = tid & 1;   // staging: row 0..63, 16-ch half
    const int chof = h * 32 + shalf * 16;         // global channel base of this half

    for (int r0 = 0; r0 < 1024; r0 += 64) {
        __syncthreads();
        // (1) geometry: thread t -> r = r0 + (t>>1), group hg = t&1
        {
            int rr = r0 + (tid >> 1);
            int hg = tid & 1;
            int gg = b * 2 + hg;
            float offRow = offr[(size_t)(gg * 2048 + rr) * 64 + w];
            float offCol = offr[(size_t)(gg * 2048 + 1024 + rr) * 64 + w];
            float rows = fmaf(tanhf(offRow), 0.984375f, (float)((rr >> 5) << 1));
            float cols = fmaf(tanhf(offCol), 0.984375f, (float)((rr & 31) << 1));
            float r0f = floorf(rows), c0f = floorf(cols);
            float fr = rows - r0f, fc = cols - c0f;
            int ri = (int)r0f, ci = (int)c0f;
            bool rv0 = (ri >= 0) && (ri < 64);
            bool rv1 = (ri + 1 >= 0) && (ri + 1 < 64);
            bool cv0 = (ci >= 0) && (ci < 64);
            bool cv1 = (ci + 1 >= 0) && (ci + 1 < 64);
            s_gp[tid >> 1][hg][0] = (rv0 && cv0) ? ri * 64 + ci : -1;
            s_gp[tid >> 1][hg][1] = (rv0 && cv1) ? ri * 64 + ci + 1 : -1;
            s_gp[tid >> 1][hg][2] = (rv1 && cv0) ? (ri + 1) * 64 + ci : -1;
            s_gp[tid >> 1][hg][3] = (rv1 && cv1) ? (ri + 1) * 64 + ci + 1 : -1;
            s_gw[tid >> 1][hg] = make_float4((1.f - fr) * (1.f - fc), (1.f - fr) * fc,
                                             fr * (1.f - fc),         fr * fc);
        }
        __syncthreads();

        // (2) sample-stage K [r][c] and V transposed [c][r]
        {
            float ak[16], av[16];
            #pragma unroll
            for (int j = 0; j < 16; j++) {
                ak[j] = s_kb[shalf * 16 + j];
                av[j] = s_vb[shalf * 16 + j];
            }
            #pragma unroll
            for (int hg = 0; hg < 2; hg++) {
                const float4 ww = s_gw[srow][hg];
                const float wts[4] = {ww.x, ww.y, ww.z, ww.w};
                const __nv_bfloat16* pk0 =
                    pkT + (size_t)(b * 2 + hg) * HWPIX * 256 + chof;
                const __nv_bfloat16* pv0 =
                    pvT + (size_t)(b * 2 + hg) * HWPIX * 256 + chof;
                #pragma unroll
                for (int cn = 0; cn < 4; cn++) {
                    int pix = s_gp[srow][hg][cn];
                    if (pix >= 0) {
                        size_t off = (size_t)pix * 256;
                        uint4 ku0 = *(const uint4*)(pk0 + off);
                        uint4 ku1 = *(const uint4*)(pk0 + off + 8);
                        uint4 vu0 = *(const uint4*)(pv0 + off);
                        uint4 vu1 = *(const uint4*)(pv0 + off + 8);
                        float kf[16], vf[16];
                        unp8(ku0, kf); unp8(ku1, kf + 8);
                        unp8(vu0, vf); unp8(vu1, vf + 8);
                        float wt = wts[cn];
                        #pragma unroll
                        for (int j = 0; j < 16; j++) {
                            ak[j] = fmaf(kf[j], wt, ak[j]);
                            av[j] = fmaf(vf[j], wt, av[j]);
                        }
                    }
                }
            }
            #pragma unroll
            for (int j = 0; j < 16; j++) {
                Ks[srow][shalf * 16 + j] = to_tf32(ak[j]);
                VsT[shalf * 16 + j][srow] = to_tf32(av[j]);
            }
        }
        __syncthreads();

        // (3a) S[16q x 64r] per warp = Q Kt
        float S[8][4];
        #pragma unroll
        for (int nj = 0; nj < 8; nj++)
            #pragma unroll
            for (int e = 0; e < 4; e++) S[nj][e] = 0.f;
        #pragma unroll
        for (int kk = 0; kk < 4; kk++) {
            int kbx = kk * 8;
            uint32_t af[4];
            af[0] = __float_as_uint(Qs[warp * 16 + g    ][kbx + tg    ]);
            af[1] = __float_as_uint(Qs[warp * 16 + g + 8][kbx + tg    ]);
            af[2] = __float_as_uint(Qs[warp * 16 + g    ][kbx + tg + 4]);
            af[3] = __float_as_uint(Qs[warp * 16 + g + 8][kbx + tg + 4]);
            #pragma unroll
            for (int nj = 0; nj < 8; nj++) {
                uint32_t bf[2];
                bf[0] = __float_as_uint(Ks[nj * 8 + g][kbx + tg    ]);
                bf[1] = __float_as_uint(Ks[nj * 8 + g][kbx + tg + 4]);
                mma_tf32(S[nj], af, bf);
            }
        }

        // (3b) add relative-position bias
        #pragma unroll
        for (int nj = 0; nj < 8; nj++) {
            int r0c = r0 + nj * 8 + 2 * tg;
            int r1c = r0c + 1;
            int o0 = ((r0c >> 5) << 1) * 127 + ((r0c & 31) << 1);
            int o1 = ((r1c >> 5) << 1) * 127 + ((r1c & 31) << 1);
            S[nj][0] += poshA[o0];
            S[nj][1] += poshA[o1];
            S[nj][2] += poshB[o0];
            S[nj][3] += poshB[o1];
        }

        // (3c) online softmax (rows g, g+8; stats reduced over the 4 tg lanes)
        float mxA = -1e30f, mxB = -1e30f;
        #pragma unroll
        for (int nj = 0; nj < 8; nj++) {
            mxA = fmaxf(mxA, fmaxf(S[nj][0], S[nj][1]));
            mxB = fmaxf(mxB, fmaxf(S[nj][2], S[nj][3]));
        }
        mxA = fmaxf(mxA, __shfl_xor_sync(0xffffffffu, mxA, 1));
        mxA = fmaxf(mxA, __shfl_xor_sync(0xffffffffu, mxA, 2));
        mxB = fmaxf(mxB, __shfl_xor_sync(0xffffffffu, mxB, 1));
        mxB = fmaxf(mxB, __shfl_xor_sync(0xffffffffu, mxB, 2));
        float mnA = fmaxf(mA, mxA), mnB = fmaxf(mB, mxB);
        float corrA = fexp(mA - mnA), corrB = fexp(mB - mnB);
        mA = mnA; mB = mnB;

        float suA = 0.f, suB = 0.f;
        #pragma unroll
        for (int nj = 0; nj < 8; nj++) {
            float p0 = fexp(S[nj][0] - mnA);
            float p1 = fexp(S[nj][1] - mnA);
            float p2 = fexp(S[nj][2] - mnB);
            float p3 = fexp(S[nj][3] - mnB);
            suA += p0 + p1;
            suB += p2 + p3;
            int c0 = nj * 8 + 2 * tg;
            Ps[warp * 16 + g    ][c0    ] = to_tf32(p0);
            Ps[warp * 16 + g    ][c0 + 1] = to_tf32(p1);
            Ps[warp * 16 + g + 8][c0    ] = to_tf32(p2);
            Ps[warp * 16 + g + 8][c0 + 1] = to_tf32(p3);
        }
        suA += __shfl_xor_sync(0xffffffffu, suA, 1);
        suA += __shfl_xor_sync(0xffffffffu, suA, 2);
        suB += __shfl_xor_sync(0xffffffffu, suB, 1);
        suB += __shfl_xor_sync(0xffffffffu, suB, 2);
        sA = sA * corrA + suA;
        sB = sB * corrB + suB;

        // rescale O (c0,c1 = row g; c2,c3 = row g+8)
        #pragma unroll
        for (int nj = 0; nj < 4; nj++) {
            O[nj][0] *= corrA; O[nj][1] *= corrA;
            O[nj][2] *= corrB; O[nj][3] *= corrB;
        }
        __syncwarp();
        __syncthreads();

        // (3d) O += P Vt : A = Ps [16q x 64k], B = VsT [32n x 64k]
        #pragma unroll
        for (int kk = 0; kk < 8; kk++) {
            int kbx = kk * 8;
            uint32_t af[4];
            af[0] = __float_as_uint(Ps[warp * 16 + g    ][kbx + tg    ]);
            af[1] = __float_as_uint(Ps[warp * 16 + g + 8][kbx + tg    ]);
            af[2] = __float_as_uint(Ps[warp * 16 + g    ][kbx + tg + 4]);
            af[3] = __float_as_uint(Ps[warp * 16 + g + 8][kbx + tg + 4]);
            #pragma unroll
            for (int nj = 0; nj < 4; nj++) {
                uint32_t bf[2];
                bf[0] = __float_as_uint(VsT[nj * 8 + g][kbx + tg    ]);
                bf[1] = __float_as_uint(VsT[nj * 8 + g][kbx + tg + 4]);
                mma_tf32(O[nj], af, bf);
            }
        }
    }

    // epilogue: normalize and write (pixel-major, head slice)
    float invA = 1.0f / sA, invB = 1.0f / sB;
    float* opA = outT + ((size_t)b * HWPIX + yA * 64 + xA) * 256 + h * 32;
    float* opB = outT + ((size_t)b * HWPIX + yB * 64 + xB) * 256 + h * 32;
    #pragma unroll
    for (int nj = 0; nj < 4; nj++) {
        int c = nj * 8 + 2 * tg;
        opA[c]     = O[nj][0] * invA;
        opA[c + 1] = O[nj][1] * invA;
        opB[c]     = O[nj][2] * invB;
        opB[c + 1] = O[nj][3] * invB;
    }
}

// ------------------------------ launch -------------------------------------
extern "C" void kernel_launch(void* const* d_in, const int* in_sizes, int n_in,
                              void* d_out, int out_size)
{
    const float* x      = (const float*)d_in[0];
    const float* ln1_g  = (const float*)d_in[1];
    const float* ln1_b  = (const float*)d_in[2];
    const float* q_w    = (const float*)d_in[3];
    const float* q_b    = (const float*)d_in[4];
    const float* k_w    = (const float*)d_in[5];
    const float* k_b    = (const float*)d_in[6];
    const float* v_w    = (const float*)d_in[7];
    const float* v_b    = (const float*)d_in[8];
    const float* off1_w = (const float*)d_in[9];
    const float* off2_w = (const float*)d_in[10];
    const float* off3_w = (const float*)d_in[11];
    const float* bn_g   = (const float*)d_in[12];
    const float* bn_b   = (const float*)d_in[13];
    const float* bn_m   = (const float*)d_in[14];
    const float* bn_v   = (const float*)d_in[15];
    const float* off4_w = (const float*)d_in[16];
    const float* pos    = (const float*)d_in[17];
    const float* proj_w = (const float*)d_in[18];
    const float* proj_b = (const float*)d_in[19];
    const float* ln2_g  = (const float*)d_in[20];
    const float* ln2_b  = (const float*)d_in[21];
    const float* mlp_w1 = (const float*)d_in[22];
    const float* mlp_b1 = (const float*)d_in[23];
    const float* mlp_w2 = (const float*)d_in[24];
    const float* mlp_b2 = (const float*)d_in[25];
    float* out = (float*)d_out;

    float *xaT, *q, *t1, *t2, *t3, *oT, *offr, *attnT, *x2, *xmT, *hidT;
    __nv_bfloat16 *pkB, *pvB;
    cudaGetSymbolAddress((void**)&xaT,   g_xaT);
    cudaGetSymbolAddress((void**)&q,     g_q);
    cudaGetSymbolAddress((void**)&t1,    g_t1);
    cudaGetSymbolAddress((void**)&t2,    g_t2);
    cudaGetSymbolAddress((void**)&t3,    g_t3);
    cudaGetSymbolAddress((void**)&oT,    g_oT);
    cudaGetSymbolAddress((void**)&offr,  g_offr);
    cudaGetSymbolAddress((void**)&pkB,   g_pk);
    cudaGetSymbolAddress((void**)&pvB,   g_pv);
    cudaGetSymbolAddress((void**)&attnT, g_attnT);
    cudaGetSymbolAddress((void**)&x2,    g_x2);
    cudaGetSymbolAddress((void**)&xmT,   g_xmT);
    cudaGetSymbolAddress((void**)&hidT,  g_hidT);

    // 1. LN1: x (B,C,HW) C-major -> xaT pixel-major
    ln_kernel<<<8192, 256>>>(x, ln1_g, ln1_b, xaT,
                             (size_t)CDIM * HWPIX, (size_t)HWPIX, (size_t)1);

    // 2. q = q_w @ xa + q_b  -> C-major (B,256,4096)
    gemm_tn<<<dim3(HWPIX / 64, CDIM / 128, NB), 256>>>(
        q_w, CDIM, xaT, CDIM, (size_t)HWPIX * CDIM,
        q_b, nullptr, q, CDIM, HWPIX, CDIM, 0);

    // 3. offset path: 3x depthwise stride-2 convs (q viewed as (4,128,64,64))
    dw_conv<<<(4 * 128 * 32 * 32 + 255) / 256, 256>>>(q,  off1_w, t1, 64, 32);
    dw_conv<<<(4 * 128 * 16 * 16 + 255) / 256, 256>>>(t1, off2_w, t2, 32, 16);
    dw_conv<<<(4 * 128 *  8 *  8 + 255) / 256, 256>>>(t2, off3_w, t3, 16, 8);

    // 4. BN + GELU, transpose to pixel-major
    bn_gelu_t<<<(4 * 128 * 64 + 255) / 256, 256>>>(t3, bn_g, bn_b, bn_m, bn_v, oT);

    // 5. off4: (2048x128) @ (64x128)^T per group -> offr C-major (4,2048,64)
    gemm_tn<<<dim3(1, 2048 / 128, 4), 256>>>(
        off4_w, 128, oT, 128, (size_t)64 * 128,
        nullptr, nullptr, offr, 2048, 64, 128, 0);

    // 6a/6b. partial conv maps -> bf16 pixel-major (L2-resident, 8MB total)
    gemm_tn<<<dim3(HWPIX / 64, 2, 4), 256>>>(
        k_w, CDIM, xaT, CDIM, 0,
        nullptr, nullptr, (float*)pkB, CDIM, HWPIX, GC,
        GF_GROUPED | GF_OUT_NMAJOR | GF_OUT_BF16);
    gemm_tn<<<dim3(HWPIX / 64, 2, 4), 256>>>(
        v_w, CDIM, xaT, CDIM, 0,
        nullptr, nullptr, (float*)pvB, CDIM, HWPIX, GC,
        GF_GROUPED | GF_OUT_NMAJOR | GF_OUT_BF16);

    // 7. attention with fused deformable sampling -> attnT pixel-major
    attn_kernel<<<dim3(NWIN, HEADS, NB), 128>>>(
        q, offr, pkB, pvB, k_b, v_b, pos, attnT);

    // 8. proj + residual(x, C-major) -> x2 pixel-major
    gemm_tn<<<dim3(HWPIX / 64, CDIM / 128, NB), 256>>>(
        proj_w, CDIM, attnT, CDIM, (size_t)HWPIX * CDIM,
        proj_b, x, x2, CDIM, HWPIX, CDIM, GF_OUT_NMAJOR);

    // 9. LN2 on x2 (pixel-major) -> xmT pixel-major
    ln_kernel<<<8192, 256>>>(x2, ln2_g, ln2_b, xmT,
                             (size_t)HWPIX * CDIM, (size_t)1, (size_t)CDIM);

    // 10. mlp1 + gelu -> hidT pixel-major (B,4096,1024)
    gemm_tn<<<dim3(HWPIX / 64, MLPH / 128, NB), 256>>>(
        mlp_w1, CDIM, xmT, CDIM, (size_t)HWPIX * CDIM,
        mlp_b1, nullptr, hidT, MLPH, HWPIX, CDIM, GF_OUT_NMAJOR | GF_GELU);

    // 11. mlp2 + residual(x2, pixel-major) -> out C-major (B,256,64,64)
    gemm_tn<<<dim3(HWPIX / 64, CDIM / 128, NB), 256>>>(
        mlp_w2, MLPH, hidT, MLPH, (size_t)HWPIX * MLPH,
        mlp_b2, x2, out, CDIM, HWPIX, MLPH, GF_RES_NMAJOR);
}